// round 14
// baseline (speedup 1.0000x reference)
#include <cuda_runtime.h>
#include <cuda_bf16.h>
#include <math.h>

// ---------------- problem constants ----------------
#define BB 16
#define LL 512
#define HH 256
#define NHH 8
#define HDD 32
#define ITER 2
#define PCOLS 272        // NH * 34  (slots: 0=a1, 1=a2, 2..33=Fw cols)
#define NROWS (BB*LL)    // 8192
#define YROWS (BB*(LL+1))// 8208
#define NEGV  (-9e15f)

typedef unsigned long long ull;

// packed fp32x2 ops (Blackwell FFMA2 — only reachable via PTX)
#define PK2(o, lo, hi) \
    asm("mov.b64 %0, {%1, %2};" : "=l"(o) \
        : "r"(__float_as_uint(lo)), "r"(__float_as_uint(hi)))
#define FMA2(d, a, b) \
    asm("fma.rn.f32x2 %0, %1, %2, %0;" : "+l"(d) : "l"(a), "l"(b))
#define UPK2(lo, hi, in) do { unsigned int l_, h_; \
    asm("mov.b64 {%0, %1}, %2;" : "=r"(l_), "=r"(h_) : "l"(in)); \
    lo = __uint_as_float(l_); hi = __uint_as_float(h_); } while(0)

// ---------------- scratch (device globals, no alloc) ----------------
__device__ float g_W1[HH*PCOLS];
__device__ float g_W2[HH*PCOLS];
__device__ float g_W3[HH*PCOLS];
__device__ float g_cb[PCOLS];
__device__ float g_D [NROWS*PCOLS];
__device__ float g_P [NROWS*PCOLS];
__device__ float g_R [BB*PCOLS];
__device__ float g_nodes[NROWS*HH];
__device__ float g_xn   [NROWS*HH];
__device__ float g_temp [NROWS*HH];
__device__ float g_kmat [YROWS*HH];
__device__ float g_relay[BB*HH];
__device__ float g_q    [BB*HH];
__device__ float g_attv [BB*HH];
__device__ float g_skT  [2*HH*HH];
__device__ float g_sqT  [2*HH*HH];
__device__ float g_soT  [2*HH*HH];

// ---------------- weight folding ----------------
__global__ __launch_bounds__(256) void build_w1(const float* __restrict__ Wq,
        const float* __restrict__ a1, const float* __restrict__ a2,
        const float* __restrict__ fw, float* __restrict__ W1)
{
    int c = blockIdx.x;                 // 0..271
    int n = c / 34, s = c % 34;
    int t = threadIdx.x;                // 0..255
    __shared__ float cvec[256];
    float cv;
    if (s == 0)      cv = a1[n*768 + t];
    else if (s == 1) cv = a2[n*768 + t];
    else             cv = fw[(size_t)n*24576 + t*32 + (s-2)];
    cvec[t] = cv;
    __syncthreads();
    const float* wqn = Wq + (size_t)n*65536;
    float sum = 0.f;
    #pragma unroll 8
    for (int d = 0; d < 256; d++) sum += wqn[d*256 + t] * cvec[d];
    W1[t*PCOLS + c] = sum;
}

// Sections: [0,272) W2/W3 | [272,656) tiled transposes | [656,658) cb.
__global__ __launch_bounds__(256) void build_misc(const float* __restrict__ a1,
        const float* __restrict__ a2, const float* __restrict__ fw,
        const float* __restrict__ bq, const float* __restrict__ skw,
        const float* __restrict__ sqw, const float* __restrict__ sow,
        float* __restrict__ W2, float* __restrict__ W3,
        float* __restrict__ cb, float* __restrict__ skT,
        float* __restrict__ sqT, float* __restrict__ soT)
{
    __shared__ float ts[32][33];
    int blk = blockIdx.x;
    int tid = threadIdx.x;
    if (blk < 272) {
        int idx = blk*256 + tid;                // < 69632 = HH*PCOLS
        int k = idx / PCOLS, c = idx % PCOLS;
        int n = c / 34, s = c % 34;
        int re = 256 + 2*k, ro = re + 1;
        float ve, vo;
        if (s == 0)      { ve = a1[n*768+re]; vo = a1[n*768+ro]; }
        else if (s == 1) { ve = a2[n*768+re]; vo = a2[n*768+ro]; }
        else { ve = fw[(size_t)n*24576 + re*32 + (s-2)];
               vo = fw[(size_t)n*24576 + ro*32 + (s-2)]; }
        W2[idx] = ve; W3[idx] = vo;
    } else if (blk < 656) {
        int m = (blk-272) >> 6;                 // 0..5
        int t = (blk-272) & 63;
        int ti = t & 7, tj = t >> 3;
        int which = m >> 1, it = m & 1;
        const float* src = ((which==0) ? skw : (which==1) ? sqw : sow)
                           + (size_t)it*65536;
        float* dst = ((which==0) ? skT : (which==1) ? sqT : soT)
                     + (size_t)it*65536;
        int tx = tid & 31, ty = tid >> 5;       // 8 rows per pass
        int C0 = tj*32, K0 = ti*32;
        #pragma unroll
        for (int u = 0; u < 4; u++)
            ts[ty + 8*u][tx] = src[(C0 + ty + 8*u)*256 + K0 + tx];
        __syncthreads();
        #pragma unroll
        for (int u = 0; u < 4; u++)
            dst[(K0 + ty + 8*u)*256 + C0 + tx] = ts[tx][ty + 8*u];
    } else {
        int c = (blk-656)*256 + tid;
        if (c < PCOLS) {
            int n = c / 34, s = c % 34;
            float sum = 0.f;
            for (int d = 0; d < 256; d++) {
                float cv = (s==0) ? a1[n*768+d] : (s==1) ? a2[n*768+d]
                         : fw[(size_t)n*24576 + d*32 + (s-2)];
                sum += bq[n*256+d] * cv;
            }
            cb[c] = sum;
        }
    }
}

__global__ __launch_bounds__(256) void relay_init(const float* __restrict__ data,
                                                  float* __restrict__ relay)
{
    int b = blockIdx.x, h = threadIdx.x;
    float s = 0.f;
    for (int l = 0; l < LL; l++) s += data[((size_t)b*LL + l)*HH + h];
    relay[b*HH + h] = s * (1.f/512.f);
}

// ---------------- GEMM: C[M,N] = A[M,256] @ B[256,N] (+ epilogue) ----------
// 128x64 block tile, 256 threads, 8x4/thread. f32x2 inner loop: A row-pairs
// read as ulonglong2 from As; B stored DUPLICATED (b,b) so pairs are direct
// 64-bit loads. Zero repack MOVs. Register prefetch of next k-tile.
#define EP_BIAS 1
#define EP_FC   2   // leaky-relu + residual + pad-mask
#define AMODE_Y 4   // A rows come from [relay_b ; nodes_b]
#define EP_PD   8   // += D + R(broadcast per batch)
__global__ __launch_bounds__(256) void gemm_kernel(const float* __restrict__ A,
        const float* __restrict__ Bm, const float* __restrict__ bias,
        float* __restrict__ C, int M, int N, int mode,
        const float* __restrict__ relayv, const float* __restrict__ resid,
        const float* __restrict__ Dm, const float* __restrict__ Rm,
        const int* __restrict__ maskp)
{
    __shared__ __align__(16) float As[16][128];
    __shared__ __align__(16) float Bs2[16][128];  // duplicated pairs
    int tid = threadIdx.x;
    int row0 = blockIdx.x * 128;
    int col0 = blockIdx.y * 64;
    int tx = tid & 15;          // col group (x4)
    int ty = tid >> 4;          // row group (x8)
    int aRow = tid & 127;       // A-load row
    int kqBase = (tid >> 7) * 2;// 0 or 2
    int bRow = tid >> 4;        // 0..15
    int bCol = (tid & 15) * 4;  // 0..60

    // fixed per-thread source pointers
    const float* arow = nullptr;
    {
        int gr = row0 + aRow;
        if (gr < M) {
            if (mode & AMODE_Y) {
                int b = gr / 513, lr = gr - b*513;
                arow = (lr == 0) ? (relayv + b*HH)
                                 : (A + (size_t)(b*LL + lr - 1)*HH);
            } else arow = A + (size_t)gr*256;
        }
    }
    bool bValid = (col0 + bCol + 4 <= N);
    const float* bptr = Bm + (size_t)bRow*N + col0 + bCol;

    ull acc2[4][4];             // rows (2i,2i+1) packed, col j
    #pragma unroll
    for (int i = 0; i < 4; i++)
        #pragma unroll
        for (int j = 0; j < 4; j++) acc2[i][j] = 0ull;

    // prologue: fetch tile 0 into registers
    float4 aReg0 = make_float4(0,0,0,0), aReg1 = make_float4(0,0,0,0);
    float4 bReg  = make_float4(0,0,0,0);
    if (arow) {
        aReg0 = *(const float4*)(arow + kqBase*4);
        aReg1 = *(const float4*)(arow + kqBase*4 + 4);
    }
    if (bValid) bReg = *(const float4*)bptr;

    for (int kt = 0; kt < 16; kt++) {
        // commit current regs to smem (A transposed, B duplicated)
        As[kqBase*4+0][aRow] = aReg0.x; As[kqBase*4+1][aRow] = aReg0.y;
        As[kqBase*4+2][aRow] = aReg0.z; As[kqBase*4+3][aRow] = aReg0.w;
        As[kqBase*4+4][aRow] = aReg1.x; As[kqBase*4+5][aRow] = aReg1.y;
        As[kqBase*4+6][aRow] = aReg1.z; As[kqBase*4+7][aRow] = aReg1.w;
        *(float4*)&Bs2[bRow][bCol*2]     = make_float4(bReg.x, bReg.x,
                                                       bReg.y, bReg.y);
        *(float4*)&Bs2[bRow][bCol*2 + 4] = make_float4(bReg.z, bReg.z,
                                                       bReg.w, bReg.w);
        __syncthreads();

        // issue next tile's loads (latency overlapped with compute below)
        if (kt < 15) {
            int k0 = (kt+1)*16;
            if (arow) {
                aReg0 = *(const float4*)(arow + k0 + kqBase*4);
                aReg1 = *(const float4*)(arow + k0 + kqBase*4 + 4);
            }
            if (bValid) bReg = *(const float4*)(bptr + (size_t)k0*N);
        }

        #pragma unroll
        for (int kk = 0; kk < 16; kk++) {
            ulonglong2 aP0 = *(const ulonglong2*)&As[kk][ty*8];
            ulonglong2 aP1 = *(const ulonglong2*)&As[kk][ty*8+4];
            ulonglong2 bP0 = *(const ulonglong2*)&Bs2[kk][tx*8];
            ulonglong2 bP1 = *(const ulonglong2*)&Bs2[kk][tx*8+4];
            FMA2(acc2[0][0], aP0.x, bP0.x);
            FMA2(acc2[0][1], aP0.x, bP0.y);
            FMA2(acc2[0][2], aP0.x, bP1.x);
            FMA2(acc2[0][3], aP0.x, bP1.y);
            FMA2(acc2[1][0], aP0.y, bP0.x);
            FMA2(acc2[1][1], aP0.y, bP0.y);
            FMA2(acc2[1][2], aP0.y, bP1.x);
            FMA2(acc2[1][3], aP0.y, bP1.y);
            FMA2(acc2[2][0], aP1.x, bP0.x);
            FMA2(acc2[2][1], aP1.x, bP0.y);
            FMA2(acc2[2][2], aP1.x, bP1.x);
            FMA2(acc2[2][3], aP1.x, bP1.y);
            FMA2(acc2[3][0], aP1.y, bP0.x);
            FMA2(acc2[3][1], aP1.y, bP0.y);
            FMA2(acc2[3][2], aP1.y, bP1.x);
            FMA2(acc2[3][3], aP1.y, bP1.y);
        }
        __syncthreads();
    }
    #pragma unroll
    for (int i2 = 0; i2 < 4; i2++) {
        #pragma unroll
        for (int p = 0; p < 2; p++) {
            int r = row0 + ty*8 + 2*i2 + p;
            if (r >= M) continue;
            int b = r >> 9, l = r & 511;
            #pragma unroll
            for (int j = 0; j < 4; j++) {
                int c = col0 + tx*4 + j;
                if (c >= N) continue;
                float vlo, vhi;
                UPK2(vlo, vhi, acc2[i2][j]);
                float v = p ? vhi : vlo;
                if (mode & EP_BIAS) v += bias[c];
                if (mode & EP_PD)
                    v += Dm[(size_t)r*N + c] + Rm[b*PCOLS + c];
                if (mode & EP_FC) {
                    v = v > 0.f ? v : 0.01f*v;
                    v += resid[(size_t)r*N + c];
                    if (maskp[b*LL + l] == 0) v = 0.f;
                }
                C[(size_t)r*N + c] = v;
            }
        }
    }
}

// ---------------- LayerNorm: warp-per-row, vectorized ----------------
__global__ __launch_bounds__(256) void ln_kernel(const float* __restrict__ nodes,
        const float* __restrict__ gam, const float* __restrict__ bet,
        float* __restrict__ xn)
{
    __shared__ float gsh[256], bsh[256];
    int tid = threadIdx.x;
    gsh[tid] = gam[tid];
    bsh[tid] = bet[tid];
    __syncthreads();
    int warp = tid >> 5, lane = tid & 31;
    int r = blockIdx.x*8 + warp;
    const float4* row = (const float4*)(nodes + (size_t)r*HH);
    float4 v0 = row[lane*2];
    float4 v1 = row[lane*2+1];
    float s  = v0.x+v0.y+v0.z+v0.w + v1.x+v1.y+v1.z+v1.w;
    float s2 = v0.x*v0.x+v0.y*v0.y+v0.z*v0.z+v0.w*v0.w
             + v1.x*v1.x+v1.y*v1.y+v1.z*v1.z+v1.w*v1.w;
    #pragma unroll
    for (int off = 16; off; off >>= 1) {
        s  += __shfl_xor_sync(0xffffffffu, s,  off);
        s2 += __shfl_xor_sync(0xffffffffu, s2, off);
    }
    float m = s * (1.f/256.f);
    float var = s2 * (1.f/256.f) - m*m;
    float rinv = rsqrtf(var + 1e-5f);
    int c0 = lane*8;
    float4 o0, o1;
    o0.x = (v0.x-m)*rinv*gsh[c0+0] + bsh[c0+0];
    o0.y = (v0.y-m)*rinv*gsh[c0+1] + bsh[c0+1];
    o0.z = (v0.z-m)*rinv*gsh[c0+2] + bsh[c0+2];
    o0.w = (v0.w-m)*rinv*gsh[c0+3] + bsh[c0+3];
    o1.x = (v1.x-m)*rinv*gsh[c0+4] + bsh[c0+4];
    o1.y = (v1.y-m)*rinv*gsh[c0+5] + bsh[c0+5];
    o1.z = (v1.z-m)*rinv*gsh[c0+6] + bsh[c0+6];
    o1.w = (v1.w-m)*rinv*gsh[c0+7] + bsh[c0+7];
    float4* orow = (float4*)(xn + (size_t)r*HH);
    orow[lane*2]   = o0;
    orow[lane*2+1] = o1;
}

// ---------------- relay projection: R = relay @ W3 ----------------
__global__ void relayproj(const float* __restrict__ relay,
        const float* __restrict__ W3, float* __restrict__ R)
{
    int b = blockIdx.x, c = threadIdx.x; // 272 threads
    __shared__ float vsh[256];
    if (c < 256) vsh[c] = relay[b*HH + c];
    __syncthreads();
    float s = 0.f;
    #pragma unroll 8
    for (int k = 0; k < 256; k++) s += vsh[k] * W3[k*PCOLS + c];
    R[b*PCOLS + c] = s;
}

// ---------------- GAT attention v5 (measured-best at 781): ---------------
// g in registers, merged phases, 135KB smem.
__global__ __launch_bounds__(512) void gat_att(const float* __restrict__ P,
        const float* __restrict__ Fb, const int* __restrict__ edge,
        float* __restrict__ temp)
{
    extern __shared__ __align__(16) float sm[];
    float* wsh  = sm;                 // [16 pairs][512 j][2]  (64KB)
    float* red  = wsh + 16*1024;      // [16 warps][32 rows][32 d] (64KB)
    float* eish = red + 16*1024;      // [512]
    float* ejsh = eish + 512;         // [512]
    float* ssh  = ejsh + 512;         // [2][32] double-buffered

    int blk = blockIdx.x;
    int n = blk >> 4, b = blk & 15;
    int tid = threadIdx.x;
    int base = n * 34;
    int lane = tid & 31;
    int warp = tid >> 5;              // 0..15

    if (tid < 512) {
        size_t idx = (size_t)(b*LL + tid)*PCOLS + base;
        eish[tid] = P[idx];
        ejsh[tid] = P[idx+1];
    }
    int js = warp * 32;
    float grv[32];
    #pragma unroll
    for (int jj = 0; jj < 32; jj++)
        grv[jj] = P[(size_t)(b*LL + js + jj)*PCOLS + base + 2 + lane];
    float Fbv = Fb[n*32 + lane];
    __syncthreads();

    const int* eb = edge + (size_t)b*LL*LL;

    for (int ch = 0; ch < 16; ch++) {
        int row0 = ch * 32;
        float wa[16], wb[16], sA, sB;
        #pragma unroll
        for (int pr = 0; pr < 2; pr++) {
            int r = row0 + 2*warp + pr;
            float ei = eish[r];
            const int4* erow4 = (const int4*)(eb + (size_t)r*LL);
            const float4* ejsh4 = (const float4*)ejsh;
            float* wv = pr ? wb : wa;
            float m = -INFINITY;
            #pragma unroll
            for (int t = 0; t < 4; t++) {
                int4   ev = erow4[t*32 + lane];
                float4 ej = ejsh4[t*32 + lane];
                float e0 = ei + ej.x; e0 = e0 >= 0.f ? e0 : 0.2f*e0;
                float e1 = ei + ej.y; e1 = e1 >= 0.f ? e1 : 0.2f*e1;
                float e2 = ei + ej.z; e2 = e2 >= 0.f ? e2 : 0.2f*e2;
                float e3 = ei + ej.w; e3 = e3 >= 0.f ? e3 : 0.2f*e3;
                if (ev.x <= 0) e0 = NEGV;
                if (ev.y <= 0) e1 = NEGV;
                if (ev.z <= 0) e2 = NEGV;
                if (ev.w <= 0) e3 = NEGV;
                wv[t*4+0] = e0; wv[t*4+1] = e1;
                wv[t*4+2] = e2; wv[t*4+3] = e3;
                m = fmaxf(m, fmaxf(fmaxf(e0,e1), fmaxf(e2,e3)));
            }
            #pragma unroll
            for (int off = 16; off; off >>= 1)
                m = fmaxf(m, __shfl_xor_sync(0xffffffffu, m, off));
            float s = 0.f;
            #pragma unroll
            for (int k = 0; k < 16; k++) {
                wv[k] = __expf(wv[k] - m);
                s += wv[k];
            }
            #pragma unroll
            for (int off = 16; off; off >>= 1)
                s += __shfl_xor_sync(0xffffffffu, s, off);
            if (pr) sB = s; else sA = s;
        }
        #pragma unroll
        for (int t = 0; t < 4; t++) {
            int jb = (t*32 + lane)*4;
            float4 p0 = make_float4(wa[t*4+0], wb[t*4+0], wa[t*4+1], wb[t*4+1]);
            float4 p1 = make_float4(wa[t*4+2], wb[t*4+2], wa[t*4+3], wb[t*4+3]);
            *(float4*)&wsh[warp*1024 + jb*2]     = p0;
            *(float4*)&wsh[warp*1024 + jb*2 + 4] = p1;
        }
        if (lane == 0) {
            ssh[(ch&1)*32 + 2*warp]     = sA;
            ssh[(ch&1)*32 + 2*warp + 1] = sB;
        }
        if (ch > 0) {
            int prow0 = (ch-1) * 32;
            #pragma unroll
            for (int rr = 0; rr < 2; rr++) {
                int rl = warp*2 + rr;
                float sum = 0.f;
                #pragma unroll
                for (int w2 = 0; w2 < 16; w2++)
                    sum += red[w2*1024 + rl*32 + lane];
                float outv = sum / ssh[((ch-1)&1)*32 + rl] + Fbv;
                outv = outv > 0.f ? outv : expm1f(outv);   // elu
                temp[(size_t)(b*LL + prow0 + rl)*HH + n*32 + lane] = outv;
            }
        }
        __syncthreads();

        ull acc2[16];
        #pragma unroll
        for (int r2 = 0; r2 < 16; r2++) acc2[r2] = 0ull;
        #pragma unroll
        for (int jg = 0; jg < 8; jg++) {
            int j0 = js + jg*4;
            ull g0d, g1d, g2d, g3d;
            PK2(g0d, grv[jg*4+0], grv[jg*4+0]);
            PK2(g1d, grv[jg*4+1], grv[jg*4+1]);
            PK2(g2d, grv[jg*4+2], grv[jg*4+2]);
            PK2(g3d, grv[jg*4+3], grv[jg*4+3]);
            #pragma unroll
            for (int r2 = 0; r2 < 16; r2++) {
                ulonglong2 wA = *(const ulonglong2*)&wsh[r2*1024 + j0*2];
                ulonglong2 wB = *(const ulonglong2*)&wsh[r2*1024 + j0*2 + 4];
                FMA2(acc2[r2], wA.x, g0d);
                FMA2(acc2[r2], wA.y, g1d);
                FMA2(acc2[r2], wB.x, g2d);
                FMA2(acc2[r2], wB.y, g3d);
            }
        }
        #pragma unroll
        for (int r2 = 0; r2 < 16; r2++) {
            float vlo, vhi;
            UPK2(vlo, vhi, acc2[r2]);
            red[warp*1024 + (2*r2)*32 + lane]   = vlo;
            red[warp*1024 + (2*r2+1)*32 + lane] = vhi;
        }
        __syncthreads();
    }
    {
        int prow0 = 15 * 32;
        #pragma unroll
        for (int rr = 0; rr < 2; rr++) {
            int rl = warp*2 + rr;
            float sum = 0.f;
            #pragma unroll
            for (int w2 = 0; w2 < 16; w2++)
                sum += red[w2*1024 + rl*32 + lane];
            float outv = sum / ssh[(15&1)*32 + rl] + Fbv;
            outv = outv > 0.f ? outv : expm1f(outv);   // elu
            temp[(size_t)(b*LL + prow0 + rl)*HH + n*32 + lane] = outv;
        }
    }
}

// ---------------- small vec @ W.T (coalesced via pre-transposed WT) -------
__global__ __launch_bounds__(256) void vecmm(const float* __restrict__ vin,
        const float* __restrict__ WT, const float* __restrict__ bias,
        float* __restrict__ vout, int lrelu)
{
    int b = blockIdx.x, c = threadIdx.x;
    __shared__ float vsh[256];
    vsh[c] = vin[b*HH + c];
    __syncthreads();
    float s = bias[c];
    #pragma unroll 8
    for (int k = 0; k < 256; k++) s += WT[k*256 + c] * vsh[k];
    if (lrelu) s = s > 0.f ? s : 0.01f*s;
    vout[b*HH + c] = s;
}

// ---------------- star attention (coalesced, one block per (b, head)) ----
__global__ __launch_bounds__(256) void star_att(const float* __restrict__ q,
        const float* __restrict__ kmat, const int* __restrict__ mask,
        float* __restrict__ att)
{
    __shared__ float pre[513];
    __shared__ float qsh[32];
    __shared__ float red[8][32];
    __shared__ float sden;
    int b = blockIdx.x, n = blockIdx.y;
    int warp = threadIdx.x >> 5, lane = threadIdx.x & 31;
    if (threadIdx.x < 32) qsh[lane] = q[b*HH + n*32 + lane];
    __syncthreads();
    const float scale = 0.17677669529663687f;   // 1/sqrt(32)
    const float* kb = kmat + (size_t)b*513*HH + n*32;

    for (int l = warp; l < 513; l += 8) {
        float v = qsh[lane] * kb[(size_t)l*HH + lane];
        #pragma unroll
        for (int off = 16; off; off >>= 1)
            v += __shfl_xor_sync(0xffffffffu, v, off);
        bool masked = (l > 0) && (mask[b*LL + l - 1] == 0);
        if (lane == 0) pre[l] = masked ? -INFINITY : v * scale;
    }
    __syncthreads();

    if (warp == 0) {
        float vals[17];
        float m = -INFINITY;
        #pragma unroll
        for (int t = 0; t < 17; t++) {
            int l = t*32 + lane;
            vals[t] = (l < 513) ? pre[l] : -INFINITY;
            m = fmaxf(m, vals[t]);
        }
        #pragma unroll
        for (int off = 16; off; off >>= 1)
            m = fmaxf(m, __shfl_xor_sync(0xffffffffu, m, off));
        float s = 0.f;
        #pragma unroll
        for (int t = 0; t < 17; t++) {
            int l = t*32 + lane;
            if (l < 513) {
                float w = __expf(vals[t] - m);
                pre[l] = w;
                s += w;
            }
        }
        #pragma unroll
        for (int off = 16; off; off >>= 1)
            s += __shfl_xor_sync(0xffffffffu, s, off);
        if (lane == 0) sden = s;
    }
    __syncthreads();

    float acc = 0.f;
    for (int l = warp; l < 513; l += 8)
        acc += pre[l] * kb[(size_t)l*HH + lane];
    red[warp][lane] = acc;
    __syncthreads();
    if (warp == 0) {
        float sum = 0.f;
        #pragma unroll
        for (int w2 = 0; w2 < 8; w2++) sum += red[w2][lane];
        att[b*HH + n*32 + lane] = sum / sden;
    }
}

// ---------------- launch ----------------
extern "C" void kernel_launch(void* const* d_in, const int* in_sizes, int n_in,
                              void* d_out, int out_size)
{
    const float* data   = (const float*)d_in[0];
    const float* WQw    = (const float*)d_in[1];
    const float* WQb    = (const float*)d_in[2];
    const float* a1     = (const float*)d_in[3];
    const float* a2     = (const float*)d_in[4];
    const float* fcw_g  = (const float*)d_in[5];   // gat_fc_w
    const float* fcb_g  = (const float*)d_in[6];   // gat_fc_b
    const float* norm_g = (const float*)d_in[7];
    const float* norm_b = (const float*)d_in[8];
    const float* sq_w   = (const float*)d_in[9];
    const float* sq_b   = (const float*)d_in[10];
    const float* sk_w   = (const float*)d_in[11];
    const float* sk_b   = (const float*)d_in[12];
    const float* so_w   = (const float*)d_in[13];
    const float* so_b   = (const float*)d_in[14];
    const float* fc_w   = (const float*)d_in[15];
    const float* fc_b   = (const float*)d_in[16];
    const int*   mask   = (const int*)d_in[17];
    const int*   edge   = (const int*)d_in[18];

    float *W1,*W2,*W3,*cb,*D,*P,*R,*nodes,*xn,*temp,*kmat,*relay,*qb,*attb;
    float *skT,*sqT,*soT;
    cudaGetSymbolAddress((void**)&W1, g_W1);
    cudaGetSymbolAddress((void**)&W2, g_W2);
    cudaGetSymbolAddress((void**)&W3, g_W3);
    cudaGetSymbolAddress((void**)&cb, g_cb);
    cudaGetSymbolAddress((void**)&D,  g_D);
    cudaGetSymbolAddress((void**)&P,  g_P);
    cudaGetSymbolAddress((void**)&R,  g_R);
    cudaGetSymbolAddress((void**)&nodes, g_nodes);
    cudaGetSymbolAddress((void**)&xn,    g_xn);
    cudaGetSymbolAddress((void**)&temp,  g_temp);
    cudaGetSymbolAddress((void**)&kmat,  g_kmat);
    cudaGetSymbolAddress((void**)&relay, g_relay);
    cudaGetSymbolAddress((void**)&qb,    g_q);
    cudaGetSymbolAddress((void**)&attb,  g_attv);
    cudaGetSymbolAddress((void**)&skT,   g_skT);
    cudaGetSymbolAddress((void**)&sqT,   g_sqT);
    cudaGetSymbolAddress((void**)&soT,   g_soT);

    // wsh 64K + red 64K + eish/ejsh 4K + ssh 2x32
    const int gat_smem = (16*1024 + 16*1024 + 512 + 512 + 64)
                         * sizeof(float);   // 135424 B < 227KB cap
    cudaFuncSetAttribute(gat_att, cudaFuncAttributeMaxDynamicSharedMemorySize,
                         gat_smem);

    build_w1<<<PCOLS, 256>>>(WQw, a1, a2, fcw_g, W1);
    build_misc<<<658, 256>>>(a1, a2, fcw_g, WQb, sk_w, sq_w, so_w,
                             W2, W3, cb, skT, sqT, soT);
    relay_init<<<BB, 256>>>(data, relay);
    cudaMemcpyAsync(nodes, data, (size_t)NROWS*HH*sizeof(float),
                    cudaMemcpyDeviceToDevice);
    // D = data @ W2
    gemm_kernel<<<dim3(64,5), 256>>>(data, W2, nullptr, D, NROWS, PCOLS, 0,
                                     nullptr, nullptr, nullptr, nullptr, nullptr);

    for (int i = 0; i < ITER; i++) {
        ln_kernel<<<NROWS/8, 256>>>(nodes, norm_g + i*HH, norm_b + i*HH, xn);
        relayproj<<<BB, PCOLS>>>(relay, W3, R);
        // P = xn @ W1 + cb + D + R   (everything gat_att needs)
        gemm_kernel<<<dim3(64,5), 256>>>(xn, W1, cb, P, NROWS, PCOLS,
                                         EP_BIAS|EP_PD, nullptr, nullptr,
                                         D, R, nullptr);
        gat_att<<<128, 512, gat_smem>>>(P, fcb_g, edge, temp);
        // nodes = mask( nodes + leaky(temp @ fc_w + fc_b) )
        gemm_kernel<<<dim3(64,4), 256>>>(temp, fc_w, fc_b, nodes, NROWS, HH,
                                         EP_BIAS|EP_FC, nullptr, nodes,
                                         nullptr, nullptr, mask);
        vecmm<<<BB, 256>>>(relay, sqT + (size_t)i*65536, sq_b + i*HH, qb, 0);
        gemm_kernel<<<dim3(65,4), 256>>>(nodes, skT + (size_t)i*65536,
                                         sk_b + i*HH, kmat, YROWS, HH,
                                         EP_BIAS|AMODE_Y, relay, nullptr,
                                         nullptr, nullptr, nullptr);
        star_att<<<dim3(BB, NHH), 256>>>(qb, kmat, mask, attb);
        vecmm<<<BB, 256>>>(attb, soT + (size_t)i*65536, so_b + i*HH, relay, 1);
    }

    cudaMemcpyAsync(d_out, nodes, (size_t)NROWS*HH*sizeof(float),
                    cudaMemcpyDeviceToDevice);
    cudaMemcpyAsync((float*)d_out + (size_t)NROWS*HH, relay,
                    (size_t)BB*HH*sizeof(float), cudaMemcpyDeviceToDevice);
}

// round 16
// speedup vs baseline: 1.2332x; 1.2332x over previous
#include <cuda_runtime.h>
#include <cuda_bf16.h>
#include <math.h>

// ---------------- problem constants ----------------
#define BB 16
#define LL 512
#define HH 256
#define NHH 8
#define HDD 32
#define ITER 2
#define PCOLS 272        // NH * 34  (slots: 0=a1, 1=a2, 2..33=Fw cols)
#define NROWS (BB*LL)    // 8192
#define YROWS (BB*(LL+1))// 8208
#define NEGV  (-9e15f)

typedef unsigned long long ull;

// packed fp32x2 ops (Blackwell FFMA2 — register-resident operands only;
// measured WIN in gat_att, measured LOSS in shared-operand GEMMs)
#define PK2(o, lo, hi) \
    asm("mov.b64 %0, {%1, %2};" : "=l"(o) \
        : "r"(__float_as_uint(lo)), "r"(__float_as_uint(hi)))
#define FMA2(d, a, b) \
    asm("fma.rn.f32x2 %0, %1, %2, %0;" : "+l"(d) : "l"(a), "l"(b))
#define UPK2(lo, hi, in) do { unsigned int l_, h_; \
    asm("mov.b64 {%0, %1}, %2;" : "=r"(l_), "=r"(h_) : "l"(in)); \
    lo = __uint_as_float(l_); hi = __uint_as_float(h_); } while(0)

// ---------------- scratch (device globals, no alloc) ----------------
__device__ float g_W1[HH*PCOLS];
__device__ float g_W2[HH*PCOLS];
__device__ float g_W3[HH*PCOLS];
__device__ float g_cb[PCOLS];
__device__ float g_D [NROWS*PCOLS];
__device__ float g_P [NROWS*PCOLS];
__device__ float g_R [BB*PCOLS];
__device__ float g_nodes[NROWS*HH];
__device__ float g_xn   [NROWS*HH];
__device__ float g_temp [NROWS*HH];
__device__ float g_kmat [YROWS*HH];
__device__ float g_relay[BB*HH];
__device__ float g_q    [BB*HH];
__device__ float g_attv [BB*HH];
__device__ float g_skT  [2*HH*HH];
__device__ float g_sqT  [2*HH*HH];
__device__ float g_soT  [2*HH*HH];

// ---------------- weight folding ----------------
__global__ __launch_bounds__(256) void build_w1(const float* __restrict__ Wq,
        const float* __restrict__ a1, const float* __restrict__ a2,
        const float* __restrict__ fw, float* __restrict__ W1)
{
    int c = blockIdx.x;                 // 0..271
    int n = c / 34, s = c % 34;
    int t = threadIdx.x;                // 0..255
    __shared__ float cvec[256];
    float cv;
    if (s == 0)      cv = a1[n*768 + t];
    else if (s == 1) cv = a2[n*768 + t];
    else             cv = fw[(size_t)n*24576 + t*32 + (s-2)];
    cvec[t] = cv;
    __syncthreads();
    const float* wqn = Wq + (size_t)n*65536;
    float sum = 0.f;
    #pragma unroll 8
    for (int d = 0; d < 256; d++) sum += wqn[d*256 + t] * cvec[d];
    W1[t*PCOLS + c] = sum;
}

// Sections: [0,272) W2/W3 | [272,656) tiled transposes | [656,658) cb.
__global__ __launch_bounds__(256) void build_misc(const float* __restrict__ a1,
        const float* __restrict__ a2, const float* __restrict__ fw,
        const float* __restrict__ bq, const float* __restrict__ skw,
        const float* __restrict__ sqw, const float* __restrict__ sow,
        float* __restrict__ W2, float* __restrict__ W3,
        float* __restrict__ cb, float* __restrict__ skT,
        float* __restrict__ sqT, float* __restrict__ soT)
{
    __shared__ float ts[32][33];
    int blk = blockIdx.x;
    int tid = threadIdx.x;
    if (blk < 272) {
        int idx = blk*256 + tid;                // < 69632 = HH*PCOLS
        int k = idx / PCOLS, c = idx % PCOLS;
        int n = c / 34, s = c % 34;
        int re = 256 + 2*k, ro = re + 1;
        float ve, vo;
        if (s == 0)      { ve = a1[n*768+re]; vo = a1[n*768+ro]; }
        else if (s == 1) { ve = a2[n*768+re]; vo = a2[n*768+ro]; }
        else { ve = fw[(size_t)n*24576 + re*32 + (s-2)];
               vo = fw[(size_t)n*24576 + ro*32 + (s-2)]; }
        W2[idx] = ve; W3[idx] = vo;
    } else if (blk < 656) {
        int m = (blk-272) >> 6;                 // 0..5
        int t = (blk-272) & 63;
        int ti = t & 7, tj = t >> 3;
        int which = m >> 1, it = m & 1;
        const float* src = ((which==0) ? skw : (which==1) ? sqw : sow)
                           + (size_t)it*65536;
        float* dst = ((which==0) ? skT : (which==1) ? sqT : soT)
                     + (size_t)it*65536;
        int tx = tid & 31, ty = tid >> 5;       // 8 rows per pass
        int C0 = tj*32, K0 = ti*32;
        #pragma unroll
        for (int u = 0; u < 4; u++)
            ts[ty + 8*u][tx] = src[(C0 + ty + 8*u)*256 + K0 + tx];
        __syncthreads();
        #pragma unroll
        for (int u = 0; u < 4; u++)
            dst[(K0 + ty + 8*u)*256 + C0 + tx] = ts[tx][ty + 8*u];
    } else {
        int c = (blk-656)*256 + tid;
        if (c < PCOLS) {
            int n = c / 34, s = c % 34;
            float sum = 0.f;
            for (int d = 0; d < 256; d++) {
                float cv = (s==0) ? a1[n*768+d] : (s==1) ? a2[n*768+d]
                         : fw[(size_t)n*24576 + d*32 + (s-2)];
                sum += bq[n*256+d] * cv;
            }
            cb[c] = sum;
        }
    }
}

__global__ __launch_bounds__(256) void relay_init(const float* __restrict__ data,
                                                  float* __restrict__ relay)
{
    int b = blockIdx.x, h = threadIdx.x;
    float s = 0.f;
    for (int l = 0; l < LL; l++) s += data[((size_t)b*LL + l)*HH + h];
    relay[b*HH + h] = s * (1.f/512.f);
}

// ---------------- GEMM: C[M,N] = A[M,256] @ B[256,N] (+ epilogue) ----------
// 128x64 block tile, 256 threads, 8x4/thread, plain FFMA, register prefetch.
// __launch_bounds__(256,3): cap regs at 84 (have 79) -> 3 blocks/SM ->
// capacity 444 >= 320 blocks -> SINGLE WAVE (kills the 296+24 tail).
#define EP_BIAS 1
#define EP_FC   2   // leaky-relu + residual + pad-mask
#define AMODE_Y 4   // A rows come from [relay_b ; nodes_b]
#define EP_PD   8   // += D + R(broadcast per batch)
__global__ __launch_bounds__(256, 3) void gemm_kernel(const float* __restrict__ A,
        const float* __restrict__ Bm, const float* __restrict__ bias,
        float* __restrict__ C, int M, int N, int mode,
        const float* __restrict__ relayv, const float* __restrict__ resid,
        const float* __restrict__ Dm, const float* __restrict__ Rm,
        const int* __restrict__ maskp)
{
    __shared__ __align__(16) float As[16][128];
    __shared__ __align__(16) float Bs[16][64];
    int tid = threadIdx.x;
    int row0 = blockIdx.x * 128;
    int col0 = blockIdx.y * 64;
    int tx = tid & 15;          // col group (x4)
    int ty = tid >> 4;          // row group (x8)
    int aRow = tid & 127;       // A-load row
    int kqBase = (tid >> 7) * 2;// 0 or 2
    int bRow = tid >> 4;        // 0..15
    int bCol = (tid & 15) * 4;  // 0..60

    // fixed per-thread source pointers
    const float* arow = nullptr;
    {
        int gr = row0 + aRow;
        if (gr < M) {
            if (mode & AMODE_Y) {
                int b = gr / 513, lr = gr - b*513;
                arow = (lr == 0) ? (relayv + b*HH)
                                 : (A + (size_t)(b*LL + lr - 1)*HH);
            } else arow = A + (size_t)gr*256;
        }
    }
    bool bValid = (col0 + bCol + 4 <= N);
    const float* bptr = Bm + (size_t)bRow*N + col0 + bCol;

    float acc[8][4];
    #pragma unroll
    for (int i = 0; i < 8; i++)
        #pragma unroll
        for (int j = 0; j < 4; j++) acc[i][j] = 0.f;

    // prologue: fetch tile 0 into registers
    float4 aReg0 = make_float4(0,0,0,0), aReg1 = make_float4(0,0,0,0);
    float4 bReg  = make_float4(0,0,0,0);
    if (arow) {
        aReg0 = *(const float4*)(arow + kqBase*4);
        aReg1 = *(const float4*)(arow + kqBase*4 + 4);
    }
    if (bValid) bReg = *(const float4*)bptr;

    for (int kt = 0; kt < 16; kt++) {
        // commit current regs to smem
        As[kqBase*4+0][aRow] = aReg0.x; As[kqBase*4+1][aRow] = aReg0.y;
        As[kqBase*4+2][aRow] = aReg0.z; As[kqBase*4+3][aRow] = aReg0.w;
        As[kqBase*4+4][aRow] = aReg1.x; As[kqBase*4+5][aRow] = aReg1.y;
        As[kqBase*4+6][aRow] = aReg1.z; As[kqBase*4+7][aRow] = aReg1.w;
        *(float4*)&Bs[bRow][bCol] = bReg;
        __syncthreads();

        // issue next tile's loads (latency overlapped with compute below)
        if (kt < 15) {
            int k0 = (kt+1)*16;
            if (arow) {
                aReg0 = *(const float4*)(arow + k0 + kqBase*4);
                aReg1 = *(const float4*)(arow + k0 + kqBase*4 + 4);
            }
            if (bValid) bReg = *(const float4*)(bptr + (size_t)k0*N);
        }

        #pragma unroll
        for (int kk = 0; kk < 16; kk++) {
            float4 a0 = *(const float4*)&As[kk][ty*8];
            float4 a1 = *(const float4*)&As[kk][ty*8+4];
            float4 b0 = *(const float4*)&Bs[kk][tx*4];
            float ar[8] = {a0.x,a0.y,a0.z,a0.w,a1.x,a1.y,a1.z,a1.w};
            float br[4] = {b0.x,b0.y,b0.z,b0.w};
            #pragma unroll
            for (int i = 0; i < 8; i++)
                #pragma unroll
                for (int j = 0; j < 4; j++) acc[i][j] += ar[i]*br[j];
        }
        __syncthreads();
    }
    #pragma unroll
    for (int i = 0; i < 8; i++) {
        int r = row0 + ty*8 + i;
        if (r >= M) continue;
        int b = r >> 9, l = r & 511;
        #pragma unroll
        for (int j = 0; j < 4; j++) {
            int c = col0 + tx*4 + j;
            if (c >= N) continue;
            float v = acc[i][j];
            if (mode & EP_BIAS) v += bias[c];
            if (mode & EP_PD)
                v += Dm[(size_t)r*N + c] + Rm[b*PCOLS + c];
            if (mode & EP_FC) {
                v = v > 0.f ? v : 0.01f*v;
                v += resid[(size_t)r*N + c];
                if (maskp[b*LL + l] == 0) v = 0.f;
            }
            C[(size_t)r*N + c] = v;
        }
    }
}

// ---------------- LayerNorm: warp-per-row, vectorized ----------------
__global__ __launch_bounds__(256) void ln_kernel(const float* __restrict__ nodes,
        const float* __restrict__ gam, const float* __restrict__ bet,
        float* __restrict__ xn)
{
    __shared__ float gsh[256], bsh[256];
    int tid = threadIdx.x;
    gsh[tid] = gam[tid];
    bsh[tid] = bet[tid];
    __syncthreads();
    int warp = tid >> 5, lane = tid & 31;
    int r = blockIdx.x*8 + warp;
    const float4* row = (const float4*)(nodes + (size_t)r*HH);
    float4 v0 = row[lane*2];
    float4 v1 = row[lane*2+1];
    float s  = v0.x+v0.y+v0.z+v0.w + v1.x+v1.y+v1.z+v1.w;
    float s2 = v0.x*v0.x+v0.y*v0.y+v0.z*v0.z+v0.w*v0.w
             + v1.x*v1.x+v1.y*v1.y+v1.z*v1.z+v1.w*v1.w;
    #pragma unroll
    for (int off = 16; off; off >>= 1) {
        s  += __shfl_xor_sync(0xffffffffu, s,  off);
        s2 += __shfl_xor_sync(0xffffffffu, s2, off);
    }
    float m = s * (1.f/256.f);
    float var = s2 * (1.f/256.f) - m*m;
    float rinv = rsqrtf(var + 1e-5f);
    int c0 = lane*8;
    float4 o0, o1;
    o0.x = (v0.x-m)*rinv*gsh[c0+0] + bsh[c0+0];
    o0.y = (v0.y-m)*rinv*gsh[c0+1] + bsh[c0+1];
    o0.z = (v0.z-m)*rinv*gsh[c0+2] + bsh[c0+2];
    o0.w = (v0.w-m)*rinv*gsh[c0+3] + bsh[c0+3];
    o1.x = (v1.x-m)*rinv*gsh[c0+4] + bsh[c0+4];
    o1.y = (v1.y-m)*rinv*gsh[c0+5] + bsh[c0+5];
    o1.z = (v1.z-m)*rinv*gsh[c0+6] + bsh[c0+6];
    o1.w = (v1.w-m)*rinv*gsh[c0+7] + bsh[c0+7];
    float4* orow = (float4*)(xn + (size_t)r*HH);
    orow[lane*2]   = o0;
    orow[lane*2+1] = o1;
}

// ---------------- relay projection: R = relay @ W3 ----------------
__global__ void relayproj(const float* __restrict__ relay,
        const float* __restrict__ W3, float* __restrict__ R)
{
    int b = blockIdx.x, c = threadIdx.x; // 272 threads
    __shared__ float vsh[256];
    if (c < 256) vsh[c] = relay[b*HH + c];
    __syncthreads();
    float s = 0.f;
    #pragma unroll 8
    for (int k = 0; k < 256; k++) s += vsh[k] * W3[k*PCOLS + c];
    R[b*PCOLS + c] = s;
}

// ---------------- GAT attention v5 (measured-best): ----------------------
// g in registers, merged phases, 135KB smem.
__global__ __launch_bounds__(512) void gat_att(const float* __restrict__ P,
        const float* __restrict__ Fb, const int* __restrict__ edge,
        float* __restrict__ temp)
{
    extern __shared__ __align__(16) float sm[];
    float* wsh  = sm;                 // [16 pairs][512 j][2]  (64KB)
    float* red  = wsh + 16*1024;      // [16 warps][32 rows][32 d] (64KB)
    float* eish = red + 16*1024;      // [512]
    float* ejsh = eish + 512;         // [512]
    float* ssh  = ejsh + 512;         // [2][32] double-buffered

    int blk = blockIdx.x;
    int n = blk >> 4, b = blk & 15;
    int tid = threadIdx.x;
    int base = n * 34;
    int lane = tid & 31;
    int warp = tid >> 5;              // 0..15

    if (tid < 512) {
        size_t idx = (size_t)(b*LL + tid)*PCOLS + base;
        eish[tid] = P[idx];
        ejsh[tid] = P[idx+1];
    }
    int js = warp * 32;
    float grv[32];
    #pragma unroll
    for (int jj = 0; jj < 32; jj++)
        grv[jj] = P[(size_t)(b*LL + js + jj)*PCOLS + base + 2 + lane];
    float Fbv = Fb[n*32 + lane];
    __syncthreads();

    const int* eb = edge + (size_t)b*LL*LL;

    for (int ch = 0; ch < 16; ch++) {
        int row0 = ch * 32;
        float wa[16], wb[16], sA, sB;
        #pragma unroll
        for (int pr = 0; pr < 2; pr++) {
            int r = row0 + 2*warp + pr;
            float ei = eish[r];
            const int4* erow4 = (const int4*)(eb + (size_t)r*LL);
            const float4* ejsh4 = (const float4*)ejsh;
            float* wv = pr ? wb : wa;
            float m = -INFINITY;
            #pragma unroll
            for (int t = 0; t < 4; t++) {
                int4   ev = erow4[t*32 + lane];
                float4 ej = ejsh4[t*32 + lane];
                float e0 = ei + ej.x; e0 = e0 >= 0.f ? e0 : 0.2f*e0;
                float e1 = ei + ej.y; e1 = e1 >= 0.f ? e1 : 0.2f*e1;
                float e2 = ei + ej.z; e2 = e2 >= 0.f ? e2 : 0.2f*e2;
                float e3 = ei + ej.w; e3 = e3 >= 0.f ? e3 : 0.2f*e3;
                if (ev.x <= 0) e0 = NEGV;
                if (ev.y <= 0) e1 = NEGV;
                if (ev.z <= 0) e2 = NEGV;
                if (ev.w <= 0) e3 = NEGV;
                wv[t*4+0] = e0; wv[t*4+1] = e1;
                wv[t*4+2] = e2; wv[t*4+3] = e3;
                m = fmaxf(m, fmaxf(fmaxf(e0,e1), fmaxf(e2,e3)));
            }
            #pragma unroll
            for (int off = 16; off; off >>= 1)
                m = fmaxf(m, __shfl_xor_sync(0xffffffffu, m, off));
            float s = 0.f;
            #pragma unroll
            for (int k = 0; k < 16; k++) {
                wv[k] = __expf(wv[k] - m);
                s += wv[k];
            }
            #pragma unroll
            for (int off = 16; off; off >>= 1)
                s += __shfl_xor_sync(0xffffffffu, s, off);
            if (pr) sB = s; else sA = s;
        }
        #pragma unroll
        for (int t = 0; t < 4; t++) {
            int jb = (t*32 + lane)*4;
            float4 p0 = make_float4(wa[t*4+0], wb[t*4+0], wa[t*4+1], wb[t*4+1]);
            float4 p1 = make_float4(wa[t*4+2], wb[t*4+2], wa[t*4+3], wb[t*4+3]);
            *(float4*)&wsh[warp*1024 + jb*2]     = p0;
            *(float4*)&wsh[warp*1024 + jb*2 + 4] = p1;
        }
        if (lane == 0) {
            ssh[(ch&1)*32 + 2*warp]     = sA;
            ssh[(ch&1)*32 + 2*warp + 1] = sB;
        }
        if (ch > 0) {
            int prow0 = (ch-1) * 32;
            #pragma unroll
            for (int rr = 0; rr < 2; rr++) {
                int rl = warp*2 + rr;
                float sum = 0.f;
                #pragma unroll
                for (int w2 = 0; w2 < 16; w2++)
                    sum += red[w2*1024 + rl*32 + lane];
                float outv = sum / ssh[((ch-1)&1)*32 + rl] + Fbv;
                outv = outv > 0.f ? outv : expm1f(outv);   // elu
                temp[(size_t)(b*LL + prow0 + rl)*HH + n*32 + lane] = outv;
            }
        }
        __syncthreads();

        ull acc2[16];
        #pragma unroll
        for (int r2 = 0; r2 < 16; r2++) acc2[r2] = 0ull;
        #pragma unroll
        for (int jg = 0; jg < 8; jg++) {
            int j0 = js + jg*4;
            ull g0d, g1d, g2d, g3d;
            PK2(g0d, grv[jg*4+0], grv[jg*4+0]);
            PK2(g1d, grv[jg*4+1], grv[jg*4+1]);
            PK2(g2d, grv[jg*4+2], grv[jg*4+2]);
            PK2(g3d, grv[jg*4+3], grv[jg*4+3]);
            #pragma unroll
            for (int r2 = 0; r2 < 16; r2++) {
                ulonglong2 wA = *(const ulonglong2*)&wsh[r2*1024 + j0*2];
                ulonglong2 wB = *(const ulonglong2*)&wsh[r2*1024 + j0*2 + 4];
                FMA2(acc2[r2], wA.x, g0d);
                FMA2(acc2[r2], wA.y, g1d);
                FMA2(acc2[r2], wB.x, g2d);
                FMA2(acc2[r2], wB.y, g3d);
            }
        }
        #pragma unroll
        for (int r2 = 0; r2 < 16; r2++) {
            float vlo, vhi;
            UPK2(vlo, vhi, acc2[r2]);
            red[warp*1024 + (2*r2)*32 + lane]   = vlo;
            red[warp*1024 + (2*r2+1)*32 + lane] = vhi;
        }
        __syncthreads();
    }
    {
        int prow0 = 15 * 32;
        #pragma unroll
        for (int rr = 0; rr < 2; rr++) {
            int rl = warp*2 + rr;
            float sum = 0.f;
            #pragma unroll
            for (int w2 = 0; w2 < 16; w2++)
                sum += red[w2*1024 + rl*32 + lane];
            float outv = sum / ssh[(15&1)*32 + rl] + Fbv;
            outv = outv > 0.f ? outv : expm1f(outv);   // elu
            temp[(size_t)(b*LL + prow0 + rl)*HH + n*32 + lane] = outv;
        }
    }
}

// ---------------- small vec @ W.T (coalesced via pre-transposed WT) -------
__global__ __launch_bounds__(256) void vecmm(const float* __restrict__ vin,
        const float* __restrict__ WT, const float* __restrict__ bias,
        float* __restrict__ vout, int lrelu)
{
    int b = blockIdx.x, c = threadIdx.x;
    __shared__ float vsh[256];
    vsh[c] = vin[b*HH + c];
    __syncthreads();
    float s = bias[c];
    #pragma unroll 8
    for (int k = 0; k < 256; k++) s += WT[k*256 + c] * vsh[k];
    if (lrelu) s = s > 0.f ? s : 0.01f*s;
    vout[b*HH + c] = s;
}

// ---------------- star attention (coalesced, one block per (b, head)) ----
__global__ __launch_bounds__(256) void star_att(const float* __restrict__ q,
        const float* __restrict__ kmat, const int* __restrict__ mask,
        float* __restrict__ att)
{
    __shared__ float pre[513];
    __shared__ float qsh[32];
    __shared__ float red[8][32];
    __shared__ float sden;
    int b = blockIdx.x, n = blockIdx.y;
    int warp = threadIdx.x >> 5, lane = threadIdx.x & 31;
    if (threadIdx.x < 32) qsh[lane] = q[b*HH + n*32 + lane];
    __syncthreads();
    const float scale = 0.17677669529663687f;   // 1/sqrt(32)
    const float* kb = kmat + (size_t)b*513*HH + n*32;

    for (int l = warp; l < 513; l += 8) {
        float v = qsh[lane] * kb[(size_t)l*HH + lane];
        #pragma unroll
        for (int off = 16; off; off >>= 1)
            v += __shfl_xor_sync(0xffffffffu, v, off);
        bool masked = (l > 0) && (mask[b*LL + l - 1] == 0);
        if (lane == 0) pre[l] = masked ? -INFINITY : v * scale;
    }
    __syncthreads();

    if (warp == 0) {
        float vals[17];
        float m = -INFINITY;
        #pragma unroll
        for (int t = 0; t < 17; t++) {
            int l = t*32 + lane;
            vals[t] = (l < 513) ? pre[l] : -INFINITY;
            m = fmaxf(m, vals[t]);
        }
        #pragma unroll
        for (int off = 16; off; off >>= 1)
            m = fmaxf(m, __shfl_xor_sync(0xffffffffu, m, off));
        float s = 0.f;
        #pragma unroll
        for (int t = 0; t < 17; t++) {
            int l = t*32 + lane;
            if (l < 513) {
                float w = __expf(vals[t] - m);
                pre[l] = w;
                s += w;
            }
        }
        #pragma unroll
        for (int off = 16; off; off >>= 1)
            s += __shfl_xor_sync(0xffffffffu, s, off);
        if (lane == 0) sden = s;
    }
    __syncthreads();

    float acc = 0.f;
    for (int l = warp; l < 513; l += 8)
        acc += pre[l] * kb[(size_t)l*HH + lane];
    red[warp][lane] = acc;
    __syncthreads();
    if (warp == 0) {
        float sum = 0.f;
        #pragma unroll
        for (int w2 = 0; w2 < 8; w2++) sum += red[w2][lane];
        att[b*HH + n*32 + lane] = sum / sden;
    }
}

// ---------------- launch ----------------
extern "C" void kernel_launch(void* const* d_in, const int* in_sizes, int n_in,
                              void* d_out, int out_size)
{
    const float* data   = (const float*)d_in[0];
    const float* WQw    = (const float*)d_in[1];
    const float* WQb    = (const float*)d_in[2];
    const float* a1     = (const float*)d_in[3];
    const float* a2     = (const float*)d_in[4];
    const float* fcw_g  = (const float*)d_in[5];   // gat_fc_w
    const float* fcb_g  = (const float*)d_in[6];   // gat_fc_b
    const float* norm_g = (const float*)d_in[7];
    const float* norm_b = (const float*)d_in[8];
    const float* sq_w   = (const float*)d_in[9];
    const float* sq_b   = (const float*)d_in[10];
    const float* sk_w   = (const float*)d_in[11];
    const float* sk_b   = (const float*)d_in[12];
    const float* so_w   = (const float*)d_in[13];
    const float* so_b   = (const float*)d_in[14];
    const float* fc_w   = (const float*)d_in[15];
    const float* fc_b   = (const float*)d_in[16];
    const int*   mask   = (const int*)d_in[17];
    const int*   edge   = (const int*)d_in[18];

    float *W1,*W2,*W3,*cb,*D,*P,*R,*nodes,*xn,*temp,*kmat,*relay,*qb,*attb;
    float *skT,*sqT,*soT;
    cudaGetSymbolAddress((void**)&W1, g_W1);
    cudaGetSymbolAddress((void**)&W2, g_W2);
    cudaGetSymbolAddress((void**)&W3, g_W3);
    cudaGetSymbolAddress((void**)&cb, g_cb);
    cudaGetSymbolAddress((void**)&D,  g_D);
    cudaGetSymbolAddress((void**)&P,  g_P);
    cudaGetSymbolAddress((void**)&R,  g_R);
    cudaGetSymbolAddress((void**)&nodes, g_nodes);
    cudaGetSymbolAddress((void**)&xn,    g_xn);
    cudaGetSymbolAddress((void**)&temp,  g_temp);
    cudaGetSymbolAddress((void**)&kmat,  g_kmat);
    cudaGetSymbolAddress((void**)&relay, g_relay);
    cudaGetSymbolAddress((void**)&qb,    g_q);
    cudaGetSymbolAddress((void**)&attb,  g_attv);
    cudaGetSymbolAddress((void**)&skT,   g_skT);
    cudaGetSymbolAddress((void**)&sqT,   g_sqT);
    cudaGetSymbolAddress((void**)&soT,   g_soT);

    // wsh 64K + red 64K + eish/ejsh 4K + ssh 2x32
    const int gat_smem = (16*1024 + 16*1024 + 512 + 512 + 64)
                         * sizeof(float);   // 135424 B < 227KB cap
    cudaFuncSetAttribute(gat_att, cudaFuncAttributeMaxDynamicSharedMemorySize,
                         gat_smem);

    build_w1<<<PCOLS, 256>>>(WQw, a1, a2, fcw_g, W1);
    build_misc<<<658, 256>>>(a1, a2, fcw_g, WQb, sk_w, sq_w, so_w,
                             W2, W3, cb, skT, sqT, soT);
    relay_init<<<BB, 256>>>(data, relay);
    cudaMemcpyAsync(nodes, data, (size_t)NROWS*HH*sizeof(float),
                    cudaMemcpyDeviceToDevice);
    // D = data @ W2
    gemm_kernel<<<dim3(64,5), 256>>>(data, W2, nullptr, D, NROWS, PCOLS, 0,
                                     nullptr, nullptr, nullptr, nullptr, nullptr);

    for (int i = 0; i < ITER; i++) {
        ln_kernel<<<NROWS/8, 256>>>(nodes, norm_g + i*HH, norm_b + i*HH, xn);
        relayproj<<<BB, PCOLS>>>(relay, W3, R);
        // P = xn @ W1 + cb + D + R   (everything gat_att needs)
        gemm_kernel<<<dim3(64,5), 256>>>(xn, W1, cb, P, NROWS, PCOLS,
                                         EP_BIAS|EP_PD, nullptr, nullptr,
                                         D, R, nullptr);
        gat_att<<<128, 512, gat_smem>>>(P, fcb_g, edge, temp);
        // nodes = mask( nodes + leaky(temp @ fc_w + fc_b) )
        gemm_kernel<<<dim3(64,4), 256>>>(temp, fc_w, fc_b, nodes, NROWS, HH,
                                         EP_BIAS|EP_FC, nullptr, nodes,
                                         nullptr, nullptr, mask);
        vecmm<<<BB, 256>>>(relay, sqT + (size_t)i*65536, sq_b + i*HH, qb, 0);
        gemm_kernel<<<dim3(65,4), 256>>>(nodes, skT + (size_t)i*65536,
                                         sk_b + i*HH, kmat, YROWS, HH,
                                         EP_BIAS|AMODE_Y, relay, nullptr,
                                         nullptr, nullptr, nullptr);
        star_att<<<dim3(BB, NHH), 256>>>(qb, kmat, mask, attb);
        vecmm<<<BB, 256>>>(attb, soT + (size_t)i*65536, so_b + i*HH, relay, 1);
    }

    cudaMemcpyAsync(d_out, nodes, (size_t)NROWS*HH*sizeof(float),
                    cudaMemcpyDeviceToDevice);
    cudaMemcpyAsync((float*)d_out + (size_t)NROWS*HH, relay,
                    (size_t)BB*HH*sizeof(float), cudaMemcpyDeviceToDevice);
}

// round 17
// speedup vs baseline: 1.2727x; 1.0320x over previous
#include <cuda_runtime.h>
#include <cuda_bf16.h>
#include <math.h>

// ---------------- problem constants ----------------
#define BB 16
#define LL 512
#define HH 256
#define NHH 8
#define HDD 32
#define ITER 2
#define PCOLS 272        // NH * 34  (slots: 0=a1, 1=a2, 2..33=Fw cols)
#define NROWS (BB*LL)    // 8192
#define YROWS (BB*(LL+1))// 8208
#define NEGV  (-9e15f)

typedef unsigned long long ull;

// packed fp32x2 ops (Blackwell FFMA2 — register-resident operands only;
// measured WIN in gat_att, measured LOSS in shared-operand GEMMs)
#define PK2(o, lo, hi) \
    asm("mov.b64 %0, {%1, %2};" : "=l"(o) \
        : "r"(__float_as_uint(lo)), "r"(__float_as_uint(hi)))
#define FMA2(d, a, b) \
    asm("fma.rn.f32x2 %0, %1, %2, %0;" : "+l"(d) : "l"(a), "l"(b))
#define UPK2(lo, hi, in) do { unsigned int l_, h_; \
    asm("mov.b64 {%0, %1}, %2;" : "=r"(l_), "=r"(h_) : "l"(in)); \
    lo = __uint_as_float(l_); hi = __uint_as_float(h_); } while(0)

// ---------------- scratch (device globals, no alloc) ----------------
__device__ float g_W1[HH*PCOLS];
__device__ float g_W2[HH*PCOLS];
__device__ float g_W3[HH*PCOLS];
__device__ float g_cb[PCOLS];
__device__ float g_D [NROWS*PCOLS];
__device__ float g_P [NROWS*PCOLS];
__device__ float g_R [BB*PCOLS];
__device__ float g_nodes[NROWS*HH];
__device__ float g_xn   [NROWS*HH];
__device__ float g_temp [NROWS*HH];
__device__ float g_kmat [YROWS*HH];
__device__ float g_relay[BB*HH];
__device__ float g_q    [BB*HH];
__device__ float g_attv [BB*HH];
__device__ float g_skT  [2*HH*HH];
__device__ float g_sqT  [2*HH*HH];
__device__ float g_soT  [2*HH*HH];

// ---------------- weight folding ----------------
__global__ __launch_bounds__(256) void build_w1(const float* __restrict__ Wq,
        const float* __restrict__ a1, const float* __restrict__ a2,
        const float* __restrict__ fw, float* __restrict__ W1)
{
    int c = blockIdx.x;                 // 0..271
    int n = c / 34, s = c % 34;
    int t = threadIdx.x;                // 0..255
    __shared__ float cvec[256];
    float cv;
    if (s == 0)      cv = a1[n*768 + t];
    else if (s == 1) cv = a2[n*768 + t];
    else             cv = fw[(size_t)n*24576 + t*32 + (s-2)];
    cvec[t] = cv;
    __syncthreads();
    const float* wqn = Wq + (size_t)n*65536;
    float sum = 0.f;
    #pragma unroll 8
    for (int d = 0; d < 256; d++) sum += wqn[d*256 + t] * cvec[d];
    W1[t*PCOLS + c] = sum;
}

// Sections: [0,272) W2/W3 | [272,656) transposes | [656,658) cb |
//           [658,674) relay_init (one block per batch).
__global__ __launch_bounds__(256) void build_misc(const float* __restrict__ a1,
        const float* __restrict__ a2, const float* __restrict__ fw,
        const float* __restrict__ bq, const float* __restrict__ skw,
        const float* __restrict__ sqw, const float* __restrict__ sow,
        const float* __restrict__ data,
        float* __restrict__ W2, float* __restrict__ W3,
        float* __restrict__ cb, float* __restrict__ skT,
        float* __restrict__ sqT, float* __restrict__ soT,
        float* __restrict__ relay)
{
    __shared__ float ts[32][33];
    int blk = blockIdx.x;
    int tid = threadIdx.x;
    if (blk < 272) {
        int idx = blk*256 + tid;                // < 69632 = HH*PCOLS
        int k = idx / PCOLS, c = idx % PCOLS;
        int n = c / 34, s = c % 34;
        int re = 256 + 2*k, ro = re + 1;
        float ve, vo;
        if (s == 0)      { ve = a1[n*768+re]; vo = a1[n*768+ro]; }
        else if (s == 1) { ve = a2[n*768+re]; vo = a2[n*768+ro]; }
        else { ve = fw[(size_t)n*24576 + re*32 + (s-2)];
               vo = fw[(size_t)n*24576 + ro*32 + (s-2)]; }
        W2[idx] = ve; W3[idx] = vo;
    } else if (blk < 656) {
        int m = (blk-272) >> 6;                 // 0..5
        int t = (blk-272) & 63;
        int ti = t & 7, tj = t >> 3;
        int which = m >> 1, it = m & 1;
        const float* src = ((which==0) ? skw : (which==1) ? sqw : sow)
                           + (size_t)it*65536;
        float* dst = ((which==0) ? skT : (which==1) ? sqT : soT)
                     + (size_t)it*65536;
        int tx = tid & 31, ty = tid >> 5;       // 8 rows per pass
        int C0 = tj*32, K0 = ti*32;
        #pragma unroll
        for (int u = 0; u < 4; u++)
            ts[ty + 8*u][tx] = src[(C0 + ty + 8*u)*256 + K0 + tx];
        __syncthreads();
        #pragma unroll
        for (int u = 0; u < 4; u++)
            dst[(K0 + ty + 8*u)*256 + C0 + tx] = ts[tx][ty + 8*u];
    } else if (blk < 658) {
        int c = (blk-656)*256 + tid;
        if (c < PCOLS) {
            int n = c / 34, s = c % 34;
            float sum = 0.f;
            for (int d = 0; d < 256; d++) {
                float cv = (s==0) ? a1[n*768+d] : (s==1) ? a2[n*768+d]
                         : fw[(size_t)n*24576 + d*32 + (s-2)];
                sum += bq[n*256+d] * cv;
            }
            cb[c] = sum;
        }
    } else {
        int b = blk - 658;                      // 0..15: relay_init
        float s = 0.f;
        for (int l = 0; l < LL; l++) s += data[((size_t)b*LL + l)*HH + tid];
        relay[b*HH + tid] = s * (1.f/512.f);
    }
}

// ---------------- GEMM: C[M,N] = A[M,256] @ B[256,N] (+ epilogue) ----------
// 128x64 block tile, 256 threads, 8x4/thread, plain FFMA, register prefetch.
#define EP_BIAS 1
#define EP_FC   2   // leaky-relu + residual + pad-mask
#define AMODE_Y 4   // A rows come from [relay_b ; nodes_b]
#define EP_PD   8   // += D + R(broadcast per batch)
__global__ __launch_bounds__(256, 3) void gemm_kernel(const float* __restrict__ A,
        const float* __restrict__ Bm, const float* __restrict__ bias,
        float* __restrict__ C, int M, int N, int mode,
        const float* __restrict__ relayv, const float* __restrict__ resid,
        const float* __restrict__ Dm, const float* __restrict__ Rm,
        const int* __restrict__ maskp)
{
    __shared__ __align__(16) float As[16][128];
    __shared__ __align__(16) float Bs[16][64];
    int tid = threadIdx.x;
    int row0 = blockIdx.x * 128;
    int col0 = blockIdx.y * 64;
    int tx = tid & 15;          // col group (x4)
    int ty = tid >> 4;          // row group (x8)
    int aRow = tid & 127;       // A-load row
    int kqBase = (tid >> 7) * 2;// 0 or 2
    int bRow = tid >> 4;        // 0..15
    int bCol = (tid & 15) * 4;  // 0..60

    // fixed per-thread source pointers
    const float* arow = nullptr;
    {
        int gr = row0 + aRow;
        if (gr < M) {
            if (mode & AMODE_Y) {
                int b = gr / 513, lr = gr - b*513;
                arow = (lr == 0) ? (relayv + b*HH)
                                 : (A + (size_t)(b*LL + lr - 1)*HH);
            } else arow = A + (size_t)gr*256;
        }
    }
    bool bValid = (col0 + bCol + 4 <= N);
    const float* bptr = Bm + (size_t)bRow*N + col0 + bCol;

    float acc[8][4];
    #pragma unroll
    for (int i = 0; i < 8; i++)
        #pragma unroll
        for (int j = 0; j < 4; j++) acc[i][j] = 0.f;

    // prologue: fetch tile 0 into registers
    float4 aReg0 = make_float4(0,0,0,0), aReg1 = make_float4(0,0,0,0);
    float4 bReg  = make_float4(0,0,0,0);
    if (arow) {
        aReg0 = *(const float4*)(arow + kqBase*4);
        aReg1 = *(const float4*)(arow + kqBase*4 + 4);
    }
    if (bValid) bReg = *(const float4*)bptr;

    for (int kt = 0; kt < 16; kt++) {
        // commit current regs to smem
        As[kqBase*4+0][aRow] = aReg0.x; As[kqBase*4+1][aRow] = aReg0.y;
        As[kqBase*4+2][aRow] = aReg0.z; As[kqBase*4+3][aRow] = aReg0.w;
        As[kqBase*4+4][aRow] = aReg1.x; As[kqBase*4+5][aRow] = aReg1.y;
        As[kqBase*4+6][aRow] = aReg1.z; As[kqBase*4+7][aRow] = aReg1.w;
        *(float4*)&Bs[bRow][bCol] = bReg;
        __syncthreads();

        // issue next tile's loads (latency overlapped with compute below)
        if (kt < 15) {
            int k0 = (kt+1)*16;
            if (arow) {
                aReg0 = *(const float4*)(arow + k0 + kqBase*4);
                aReg1 = *(const float4*)(arow + k0 + kqBase*4 + 4);
            }
            if (bValid) bReg = *(const float4*)(bptr + (size_t)k0*N);
        }

        #pragma unroll
        for (int kk = 0; kk < 16; kk++) {
            float4 a0 = *(const float4*)&As[kk][ty*8];
            float4 a1 = *(const float4*)&As[kk][ty*8+4];
            float4 b0 = *(const float4*)&Bs[kk][tx*4];
            float ar[8] = {a0.x,a0.y,a0.z,a0.w,a1.x,a1.y,a1.z,a1.w};
            float br[4] = {b0.x,b0.y,b0.z,b0.w};
            #pragma unroll
            for (int i = 0; i < 8; i++)
                #pragma unroll
                for (int j = 0; j < 4; j++) acc[i][j] += ar[i]*br[j];
        }
        __syncthreads();
    }
    #pragma unroll
    for (int i = 0; i < 8; i++) {
        int r = row0 + ty*8 + i;
        if (r >= M) continue;
        int b = r >> 9, l = r & 511;
        #pragma unroll
        for (int j = 0; j < 4; j++) {
            int c = col0 + tx*4 + j;
            if (c >= N) continue;
            float v = acc[i][j];
            if (mode & EP_BIAS) v += bias[c];
            if (mode & EP_PD)
                v += Dm[(size_t)r*N + c] + Rm[b*PCOLS + c];
            if (mode & EP_FC) {
                v = v > 0.f ? v : 0.01f*v;
                v += resid[(size_t)r*N + c];
                if (maskp[b*LL + l] == 0) v = 0.f;
            }
            C[(size_t)r*N + c] = v;
        }
    }
}

// ---------------- LayerNorm: warp-per-row, vectorized ----------------
__global__ __launch_bounds__(256) void ln_kernel(const float* __restrict__ nodes,
        const float* __restrict__ gam, const float* __restrict__ bet,
        float* __restrict__ xn)
{
    __shared__ float gsh[256], bsh[256];
    int tid = threadIdx.x;
    gsh[tid] = gam[tid];
    bsh[tid] = bet[tid];
    __syncthreads();
    int warp = tid >> 5, lane = tid & 31;
    int r = blockIdx.x*8 + warp;
    const float4* row = (const float4*)(nodes + (size_t)r*HH);
    float4 v0 = row[lane*2];
    float4 v1 = row[lane*2+1];
    float s  = v0.x+v0.y+v0.z+v0.w + v1.x+v1.y+v1.z+v1.w;
    float s2 = v0.x*v0.x+v0.y*v0.y+v0.z*v0.z+v0.w*v0.w
             + v1.x*v1.x+v1.y*v1.y+v1.z*v1.z+v1.w*v1.w;
    #pragma unroll
    for (int off = 16; off; off >>= 1) {
        s  += __shfl_xor_sync(0xffffffffu, s,  off);
        s2 += __shfl_xor_sync(0xffffffffu, s2, off);
    }
    float m = s * (1.f/256.f);
    float var = s2 * (1.f/256.f) - m*m;
    float rinv = rsqrtf(var + 1e-5f);
    int c0 = lane*8;
    float4 o0, o1;
    o0.x = (v0.x-m)*rinv*gsh[c0+0] + bsh[c0+0];
    o0.y = (v0.y-m)*rinv*gsh[c0+1] + bsh[c0+1];
    o0.z = (v0.z-m)*rinv*gsh[c0+2] + bsh[c0+2];
    o0.w = (v0.w-m)*rinv*gsh[c0+3] + bsh[c0+3];
    o1.x = (v1.x-m)*rinv*gsh[c0+4] + bsh[c0+4];
    o1.y = (v1.y-m)*rinv*gsh[c0+5] + bsh[c0+5];
    o1.z = (v1.z-m)*rinv*gsh[c0+6] + bsh[c0+6];
    o1.w = (v1.w-m)*rinv*gsh[c0+7] + bsh[c0+7];
    float4* orow = (float4*)(xn + (size_t)r*HH);
    orow[lane*2]   = o0;
    orow[lane*2+1] = o1;
}

// ---------------- relay projection: R = relay @ W3 ----------------
__global__ void relayproj(const float* __restrict__ relay,
        const float* __restrict__ W3, float* __restrict__ R)
{
    int b = blockIdx.x, c = threadIdx.x; // 272 threads
    __shared__ float vsh[256];
    if (c < 256) vsh[c] = relay[b*HH + c];
    __syncthreads();
    float s = 0.f;
    #pragma unroll 8
    for (int k = 0; k < 256; k++) s += vsh[k] * W3[k*PCOLS + c];
    R[b*PCOLS + c] = s;
}

// ---------------- GAT attention v5b: no-max softmax (|e| << 88 bound) ----
// g in registers, merged phases, 135KB smem.
__global__ __launch_bounds__(512) void gat_att(const float* __restrict__ P,
        const float* __restrict__ Fb, const int* __restrict__ edge,
        float* __restrict__ temp)
{
    extern __shared__ __align__(16) float sm[];
    float* wsh  = sm;                 // [16 pairs][512 j][2]  (64KB)
    float* red  = wsh + 16*1024;      // [16 warps][32 rows][32 d] (64KB)
    float* eish = red + 16*1024;      // [512]
    float* ejsh = eish + 512;         // [512]
    float* ssh  = ejsh + 512;         // [2][32] double-buffered

    int blk = blockIdx.x;
    int n = blk >> 4, b = blk & 15;
    int tid = threadIdx.x;
    int base = n * 34;
    int lane = tid & 31;
    int warp = tid >> 5;              // 0..15

    if (tid < 512) {
        size_t idx = (size_t)(b*LL + tid)*PCOLS + base;
        eish[tid] = P[idx];
        ejsh[tid] = P[idx+1];
    }
    int js = warp * 32;
    float grv[32];
    #pragma unroll
    for (int jj = 0; jj < 32; jj++)
        grv[jj] = P[(size_t)(b*LL + js + jj)*PCOLS + base + 2 + lane];
    float Fbv = Fb[n*32 + lane];
    __syncthreads();

    const int* eb = edge + (size_t)b*LL*LL;

    for (int ch = 0; ch < 16; ch++) {
        int row0 = ch * 32;
        float wa[16], wb[16], sA, sB;
        #pragma unroll
        for (int pr = 0; pr < 2; pr++) {
            int r = row0 + 2*warp + pr;
            float ei = eish[r];
            const int4* erow4 = (const int4*)(eb + (size_t)r*LL);
            const float4* ejsh4 = (const float4*)ejsh;
            float* wv = pr ? wb : wa;
            float s = 0.f;
            #pragma unroll
            for (int t = 0; t < 4; t++) {
                int4   ev = erow4[t*32 + lane];
                float4 ej = ejsh4[t*32 + lane];
                float e0 = ei + ej.x; e0 = e0 >= 0.f ? e0 : 0.2f*e0;
                float e1 = ei + ej.y; e1 = e1 >= 0.f ? e1 : 0.2f*e1;
                float e2 = ei + ej.z; e2 = e2 >= 0.f ? e2 : 0.2f*e2;
                float e3 = ei + ej.w; e3 = e3 >= 0.f ? e3 : 0.2f*e3;
                if (ev.x <= 0) e0 = NEGV;
                if (ev.y <= 0) e1 = NEGV;
                if (ev.z <= 0) e2 = NEGV;
                if (ev.w <= 0) e3 = NEGV;
                // |e| <= ~6 for unmasked entries -> exp safe without max;
                // masked: __expf(-9e15) saturates to exactly 0.
                e0 = __expf(e0); e1 = __expf(e1);
                e2 = __expf(e2); e3 = __expf(e3);
                wv[t*4+0] = e0; wv[t*4+1] = e1;
                wv[t*4+2] = e2; wv[t*4+3] = e3;
                s += e0 + e1 + e2 + e3;
            }
            #pragma unroll
            for (int off = 16; off; off >>= 1)
                s += __shfl_xor_sync(0xffffffffu, s, off);
            if (pr) sB = s; else sA = s;
        }
        #pragma unroll
        for (int t = 0; t < 4; t++) {
            int jb = (t*32 + lane)*4;
            float4 p0 = make_float4(wa[t*4+0], wb[t*4+0], wa[t*4+1], wb[t*4+1]);
            float4 p1 = make_float4(wa[t*4+2], wb[t*4+2], wa[t*4+3], wb[t*4+3]);
            *(float4*)&wsh[warp*1024 + jb*2]     = p0;
            *(float4*)&wsh[warp*1024 + jb*2 + 4] = p1;
        }
        if (lane == 0) {
            ssh[(ch&1)*32 + 2*warp]     = sA;
            ssh[(ch&1)*32 + 2*warp + 1] = sB;
        }
        if (ch > 0) {
            int prow0 = (ch-1) * 32;
            #pragma unroll
            for (int rr = 0; rr < 2; rr++) {
                int rl = warp*2 + rr;
                float sum = 0.f;
                #pragma unroll
                for (int w2 = 0; w2 < 16; w2++)
                    sum += red[w2*1024 + rl*32 + lane];
                float outv = sum / ssh[((ch-1)&1)*32 + rl] + Fbv;
                outv = outv > 0.f ? outv : expm1f(outv);   // elu
                temp[(size_t)(b*LL + prow0 + rl)*HH + n*32 + lane] = outv;
            }
        }
        __syncthreads();

        ull acc2[16];
        #pragma unroll
        for (int r2 = 0; r2 < 16; r2++) acc2[r2] = 0ull;
        #pragma unroll
        for (int jg = 0; jg < 8; jg++) {
            int j0 = js + jg*4;
            ull g0d, g1d, g2d, g3d;
            PK2(g0d, grv[jg*4+0], grv[jg*4+0]);
            PK2(g1d, grv[jg*4+1], grv[jg*4+1]);
            PK2(g2d, grv[jg*4+2], grv[jg*4+2]);
            PK2(g3d, grv[jg*4+3], grv[jg*4+3]);
            #pragma unroll
            for (int r2 = 0; r2 < 16; r2++) {
                ulonglong2 wA = *(const ulonglong2*)&wsh[r2*1024 + j0*2];
                ulonglong2 wB = *(const ulonglong2*)&wsh[r2*1024 + j0*2 + 4];
                FMA2(acc2[r2], wA.x, g0d);
                FMA2(acc2[r2], wA.y, g1d);
                FMA2(acc2[r2], wB.x, g2d);
                FMA2(acc2[r2], wB.y, g3d);
            }
        }
        #pragma unroll
        for (int r2 = 0; r2 < 16; r2++) {
            float vlo, vhi;
            UPK2(vlo, vhi, acc2[r2]);
            red[warp*1024 + (2*r2)*32 + lane]   = vlo;
            red[warp*1024 + (2*r2+1)*32 + lane] = vhi;
        }
        __syncthreads();
    }
    {
        int prow0 = 15 * 32;
        #pragma unroll
        for (int rr = 0; rr < 2; rr++) {
            int rl = warp*2 + rr;
            float sum = 0.f;
            #pragma unroll
            for (int w2 = 0; w2 < 16; w2++)
                sum += red[w2*1024 + rl*32 + lane];
            float outv = sum / ssh[(15&1)*32 + rl] + Fbv;
            outv = outv > 0.f ? outv : expm1f(outv);   // elu
            temp[(size_t)(b*LL + prow0 + rl)*HH + n*32 + lane] = outv;
        }
    }
}

// ---------------- small vec @ W.T (coalesced via pre-transposed WT) -------
__global__ __launch_bounds__(256) void vecmm(const float* __restrict__ vin,
        const float* __restrict__ WT, const float* __restrict__ bias,
        float* __restrict__ vout, int lrelu)
{
    int b = blockIdx.x, c = threadIdx.x;
    __shared__ float vsh[256];
    vsh[c] = vin[b*HH + c];
    __syncthreads();
    float s = bias[c];
    #pragma unroll 8
    for (int k = 0; k < 256; k++) s += WT[k*256 + c] * vsh[k];
    if (lrelu) s = s > 0.f ? s : 0.01f*s;
    vout[b*HH + c] = s;
}

// ---------------- star attention (coalesced, one block per (b, head)) ----
__global__ __launch_bounds__(256) void star_att(const float* __restrict__ q,
        const float* __restrict__ kmat, const int* __restrict__ mask,
        float* __restrict__ att)
{
    __shared__ float pre[513];
    __shared__ float qsh[32];
    __shared__ float red[8][32];
    __shared__ float sden;
    int b = blockIdx.x, n = blockIdx.y;
    int warp = threadIdx.x >> 5, lane = threadIdx.x & 31;
    if (threadIdx.x < 32) qsh[lane] = q[b*HH + n*32 + lane];
    __syncthreads();
    const float scale = 0.17677669529663687f;   // 1/sqrt(32)
    const float* kb = kmat + (size_t)b*513*HH + n*32;

    for (int l = warp; l < 513; l += 8) {
        float v = qsh[lane] * kb[(size_t)l*HH + lane];
        #pragma unroll
        for (int off = 16; off; off >>= 1)
            v += __shfl_xor_sync(0xffffffffu, v, off);
        bool masked = (l > 0) && (mask[b*LL + l - 1] == 0);
        if (lane == 0) pre[l] = masked ? -INFINITY : v * scale;
    }
    __syncthreads();

    if (warp == 0) {
        float vals[17];
        float m = -INFINITY;
        #pragma unroll
        for (int t = 0; t < 17; t++) {
            int l = t*32 + lane;
            vals[t] = (l < 513) ? pre[l] : -INFINITY;
            m = fmaxf(m, vals[t]);
        }
        #pragma unroll
        for (int off = 16; off; off >>= 1)
            m = fmaxf(m, __shfl_xor_sync(0xffffffffu, m, off));
        float s = 0.f;
        #pragma unroll
        for (int t = 0; t < 17; t++) {
            int l = t*32 + lane;
            if (l < 513) {
                float w = __expf(vals[t] - m);
                pre[l] = w;
                s += w;
            }
        }
        #pragma unroll
        for (int off = 16; off; off >>= 1)
            s += __shfl_xor_sync(0xffffffffu, s, off);
        if (lane == 0) sden = s;
    }
    __syncthreads();

    float acc = 0.f;
    for (int l = warp; l < 513; l += 8)
        acc += pre[l] * kb[(size_t)l*HH + lane];
    red[warp][lane] = acc;
    __syncthreads();
    if (warp == 0) {
        float sum = 0.f;
        #pragma unroll
        for (int w2 = 0; w2 < 8; w2++) sum += red[w2][lane];
        att[b*HH + n*32 + lane] = sum / sden;
    }
}

// ---------------- launch ----------------
extern "C" void kernel_launch(void* const* d_in, const int* in_sizes, int n_in,
                              void* d_out, int out_size)
{
    const float* data   = (const float*)d_in[0];
    const float* WQw    = (const float*)d_in[1];
    const float* WQb    = (const float*)d_in[2];
    const float* a1     = (const float*)d_in[3];
    const float* a2     = (const float*)d_in[4];
    const float* fcw_g  = (const float*)d_in[5];   // gat_fc_w
    const float* fcb_g  = (const float*)d_in[6];   // gat_fc_b
    const float* norm_g = (const float*)d_in[7];
    const float* norm_b = (const float*)d_in[8];
    const float* sq_w   = (const float*)d_in[9];
    const float* sq_b   = (const float*)d_in[10];
    const float* sk_w   = (const float*)d_in[11];
    const float* sk_b   = (const float*)d_in[12];
    const float* so_w   = (const float*)d_in[13];
    const float* so_b   = (const float*)d_in[14];
    const float* fc_w   = (const float*)d_in[15];
    const float* fc_b   = (const float*)d_in[16];
    const int*   mask   = (const int*)d_in[17];
    const int*   edge   = (const int*)d_in[18];

    float *W1,*W2,*W3,*cb,*D,*P,*R,*nodes,*xn,*temp,*kmat,*relay,*qb,*attb;
    float *skT,*sqT,*soT;
    cudaGetSymbolAddress((void**)&W1, g_W1);
    cudaGetSymbolAddress((void**)&W2, g_W2);
    cudaGetSymbolAddress((void**)&W3, g_W3);
    cudaGetSymbolAddress((void**)&cb, g_cb);
    cudaGetSymbolAddress((void**)&D,  g_D);
    cudaGetSymbolAddress((void**)&P,  g_P);
    cudaGetSymbolAddress((void**)&R,  g_R);
    cudaGetSymbolAddress((void**)&nodes, g_nodes);
    cudaGetSymbolAddress((void**)&xn,    g_xn);
    cudaGetSymbolAddress((void**)&temp,  g_temp);
    cudaGetSymbolAddress((void**)&kmat,  g_kmat);
    cudaGetSymbolAddress((void**)&relay, g_relay);
    cudaGetSymbolAddress((void**)&qb,    g_q);
    cudaGetSymbolAddress((void**)&attb,  g_attv);
    cudaGetSymbolAddress((void**)&skT,   g_skT);
    cudaGetSymbolAddress((void**)&sqT,   g_sqT);
    cudaGetSymbolAddress((void**)&soT,   g_soT);

    // wsh 64K + red 64K + eish/ejsh 4K + ssh 2x32
    const int gat_smem = (16*1024 + 16*1024 + 512 + 512 + 64)
                         * sizeof(float);   // 135424 B < 227KB cap
    cudaFuncSetAttribute(gat_att, cudaFuncAttributeMaxDynamicSharedMemorySize,
                         gat_smem);

    build_w1<<<PCOLS, 256>>>(WQw, a1, a2, fcw_g, W1);
    build_misc<<<674, 256>>>(a1, a2, fcw_g, WQb, sk_w, sq_w, so_w, data,
                             W2, W3, cb, skT, sqT, soT, relay);
    cudaMemcpyAsync(nodes, data, (size_t)NROWS*HH*sizeof(float),
                    cudaMemcpyDeviceToDevice);
    // D = data @ W2
    gemm_kernel<<<dim3(64,5), 256>>>(data, W2, nullptr, D, NROWS, PCOLS, 0,
                                     nullptr, nullptr, nullptr, nullptr, nullptr);

    for (int i = 0; i < ITER; i++) {
        ln_kernel<<<NROWS/8, 256>>>(nodes, norm_g + i*HH, norm_b + i*HH, xn);
        relayproj<<<BB, PCOLS>>>(relay, W3, R);
        // P = xn @ W1 + cb + D + R   (everything gat_att needs)
        gemm_kernel<<<dim3(64,5), 256>>>(xn, W1, cb, P, NROWS, PCOLS,
                                         EP_BIAS|EP_PD, nullptr, nullptr,
                                         D, R, nullptr);
        gat_att<<<128, 512, gat_smem>>>(P, fcb_g, edge, temp);
        // nodes = mask( nodes + leaky(temp @ fc_w + fc_b) )
        gemm_kernel<<<dim3(64,4), 256>>>(temp, fc_w, fc_b, nodes, NROWS, HH,
                                         EP_BIAS|EP_FC, nullptr, nodes,
                                         nullptr, nullptr, mask);
        vecmm<<<BB, 256>>>(relay, sqT + (size_t)i*65536, sq_b + i*HH, qb, 0);
        gemm_kernel<<<dim3(65,4), 256>>>(nodes, skT + (size_t)i*65536,
                                         sk_b + i*HH, kmat, YROWS, HH,
                                         EP_BIAS|AMODE_Y, relay, nullptr,
                                         nullptr, nullptr, nullptr);
        star_att<<<dim3(BB, NHH), 256>>>(qb, kmat, mask, attb);
        vecmm<<<BB, 256>>>(attb, soT + (size_t)i*65536, so_b + i*HH, relay, 1);
    }

    cudaMemcpyAsync(d_out, nodes, (size_t)NROWS*HH*sizeof(float),
                    cudaMemcpyDeviceToDevice);
    cudaMemcpyAsync((float*)d_out + (size_t)NROWS*HH, relay,
                    (size_t)BB*HH*sizeof(float), cudaMemcpyDeviceToDevice);
}